// round 12
// baseline (speedup 1.0000x reference)
#include <cuda_runtime.h>

// VDEncoderDecoder: stacked LSTM encoder (8->32->8->1, T=48) + decoder
// (1->2->2->1, 60 steps) + fused fc via g = fc2_w @ fc1_w.
// R11 structure (2 warps per 32-element group; warp half owns half the units,
// 12 warps/SM) + R10 port split: ~half the weight stream moved to the
// constant port (e1 W_hh gates i,f + e2 W_ih + biases), rest on smem.
// smem, const and FMA pipes balance at ~14k cyc/SM/timestep.

#define TPB 64
static constexpr int BATCH = 32768;
static constexpr int T = 48;

// constant memory (staged via D2D memcpy in kernel_launch)
__constant__ __align__(16) float4 C_E1HH_IF[512];  // w1hh rows 0..63 (gates i,f), [r*8+j]
__constant__ __align__(16) float4 C_E2IH[256];     // w2ih rows 0..31, [r*8+d]
__constant__ float CB1[128];
__constant__ float CB2[32];

// smem float offsets
static constexpr int OFF_W1IH  = 0;      // 128x8 = 1024
static constexpr int OFF_W1HGO = 1024;   // w1hh rows 64..127 (gates g,o): 2048
static constexpr int OFF_W2HH  = 3072;   // 32x8 = 256
static constexpr int OFF_W3IH  = 3328;   // 32
static constexpr int OFF_W3HH  = 3360;   // 4
static constexpr int OFF_B3    = 3364;   // 4
static constexpr int OFF_D1IH  = 3368;   // 8
static constexpr int OFF_D1HH  = 3376;   // 16
static constexpr int OFF_BD1   = 3392;   // 8
static constexpr int OFF_D2IH  = 3400;   // 16
static constexpr int OFF_D2HH  = 3416;   // 16
static constexpr int OFF_BD2   = 3432;   // 8
static constexpr int OFF_D3IH  = 3440;   // 8
static constexpr int OFF_D3HH  = 3448;   // 4
static constexpr int OFF_BD3   = 3452;   // 4
static constexpr int OFF_G     = 3456;   // 720
static constexpr int OFF_CB    = 4176;   // 12
static constexpr int OFF_H1B   = 4188;   // 32x32 = 1024
static constexpr int OFF_H2B   = 5212;   // 8x32  = 256
static constexpr int SMEM_FLOATS = 5468; // ~21.9 KB

__device__ __forceinline__ float sigf(float x) {
    return __fdividef(1.0f, 1.0f + __expf(-x));
}
__device__ __forceinline__ float tanhx(float x) {
    float e = __expf(2.0f * x);
    return 1.0f - __fdividef(2.0f, e + 1.0f);
}

// Small scalar LSTM cell (decoder path), fully unrolled.
template<int H, int DIN>
__device__ __forceinline__ void lstm_small(
    const float* __restrict__ wih, const float* __restrict__ whh,
    const float* __restrict__ bias,
    const float (&xin)[DIN], float (&h)[H], float (&c)[H])
{
    float hn[H];
#pragma unroll
    for (int u = 0; u < H; ++u) {
        float a0 = bias[u];
        float a1 = bias[H + u];
        float a2 = bias[2 * H + u];
        float a3 = bias[3 * H + u];
#pragma unroll
        for (int d = 0; d < DIN; ++d) {
            float xv = xin[d];
            a0 = fmaf(xv, wih[u * DIN + d], a0);
            a1 = fmaf(xv, wih[(H + u) * DIN + d], a1);
            a2 = fmaf(xv, wih[(2 * H + u) * DIN + d], a2);
            a3 = fmaf(xv, wih[(3 * H + u) * DIN + d], a3);
        }
#pragma unroll
        for (int j = 0; j < H; ++j) {
            float hv = h[j];
            a0 = fmaf(hv, whh[u * H + j], a0);
            a1 = fmaf(hv, whh[(H + u) * H + j], a1);
            a2 = fmaf(hv, whh[(2 * H + u) * H + j], a2);
            a3 = fmaf(hv, whh[(3 * H + u) * H + j], a3);
        }
        float ig = sigf(a0);
        float fg = sigf(a1);
        float gg = tanhx(a2);
        float og = sigf(a3);
        float cn = fmaf(fg, c[u], ig * gg);
        c[u] = cn;
        hn[u] = og * tanhx(cn);
    }
#pragma unroll
    for (int u = 0; u < H; ++u) h[u] = hn[u];
}

__global__ void __launch_bounds__(TPB, 6)
vd_encdec_kernel(
    const float* __restrict__ x,
    const float* __restrict__ w1ih, const float* __restrict__ w1hh,
    const float* __restrict__ w2hh,
    const float* __restrict__ w3ih, const float* __restrict__ w3hh, const float* __restrict__ b3,
    const float* __restrict__ d1ih, const float* __restrict__ d1hh, const float* __restrict__ bd1,
    const float* __restrict__ d2ih, const float* __restrict__ d2hh, const float* __restrict__ bd2,
    const float* __restrict__ d3ih, const float* __restrict__ d3hh, const float* __restrict__ bd3,
    const float* __restrict__ fc1w, const float* __restrict__ fc1b,
    const float* __restrict__ fc2w, const float* __restrict__ fc2b,
    float* __restrict__ out)
{
    __shared__ __align__(16) float sw[SMEM_FLOATS];
    const int tid = threadIdx.x;

    for (int i = tid; i < 1024; i += TPB) sw[OFF_W1IH + i] = w1ih[i];
    for (int i = tid; i < 2048; i += TPB) sw[OFF_W1HGO + i] = w1hh[64 * 32 + i];  // gates g,o
    for (int i = tid; i < 256;  i += TPB) sw[OFF_W2HH + i] = w2hh[i];
    for (int i = tid; i < 32;   i += TPB) sw[OFF_W3IH + i] = w3ih[i];
    if (tid < 4)  sw[OFF_W3HH + tid] = w3hh[tid];
    if (tid < 4)  sw[OFF_B3   + tid] = b3[tid];
    if (tid < 8)  sw[OFF_D1IH + tid] = d1ih[tid];
    if (tid < 16) sw[OFF_D1HH + tid] = d1hh[tid];
    if (tid < 8)  sw[OFF_BD1 + tid] = bd1[tid];
    if (tid < 16) sw[OFF_D2IH + tid] = d2ih[tid];
    if (tid < 16) sw[OFF_D2HH + tid] = d2hh[tid];
    if (tid < 8)  sw[OFF_BD2 + tid] = bd2[tid];
    if (tid < 8)  sw[OFF_D3IH + tid] = d3ih[tid];
    if (tid < 4)  sw[OFF_D3HH + tid] = d3hh[tid];
    if (tid < 4)  sw[OFF_BD3 + tid] = bd3[tid];
    for (int i = tid; i < 720; i += TPB) {
        int t = i / 12, j = i % 12;
        float a = 0.0f;
        for (int k = 0; k < 32; ++k)
            a = fmaf(fc2w[j * 32 + k], fc1w[k * 60 + t], a);
        sw[OFF_G + i] = a;
    }
    if (tid < 12) {
        float a = fc2b[tid];
        for (int k = 0; k < 32; ++k)
            a = fmaf(fc2w[tid * 32 + k], fc1b[k], a);
        sw[OFF_CB + tid] = a;
    }
    __syncthreads();

    const int lane = tid & 31;
    const int half = tid >> 5;
    const int elem = blockIdx.x * 32 + lane;
    const float* xe = x + (size_t)elem * (T * 8);
    const int ub1 = half * 16;
    const int ub2 = half * 4;

    float h1[32], h2[8];
    float c1l[16], c2l[4];
    float h3[1], c3[1];
    float hd1[2], cd1[2], hd2[2], cd2[2], hd3[1], cd3[1];
    float acc[12];
#pragma unroll
    for (int i = 0; i < 32; ++i) h1[i] = 0.0f;
#pragma unroll
    for (int i = 0; i < 16; ++i) c1l[i] = 0.0f;
#pragma unroll
    for (int i = 0; i < 8; ++i) h2[i] = 0.0f;
#pragma unroll
    for (int i = 0; i < 4; ++i) c2l[i] = 0.0f;
    h3[0] = 0.0f; c3[0] = 0.0f;
#pragma unroll
    for (int i = 0; i < 2; ++i) { hd1[i] = 0.0f; cd1[i] = 0.0f; hd2[i] = 0.0f; cd2[i] = 0.0f; }
    hd3[0] = 0.0f; cd3[0] = 0.0f;
#pragma unroll
    for (int i = 0; i < 12; ++i) acc[i] = 0.0f;

    // ---- fused steps t = 0..47 ----
#pragma unroll 1
    for (int t = 0; t < T; ++t) {
        float4 xa = *reinterpret_cast<const float4*>(xe + t * 8);
        float4 xc = *reinterpret_cast<const float4*>(xe + t * 8 + 4);
        float xr[8] = { xa.x, xa.y, xa.z, xa.w, xc.x, xc.y, xc.z, xc.w };

        // ---- e1: my 16 units, gates i,f from CONST, gates g,o from SMEM ----
#pragma unroll 1
        for (int uu = 0; uu < 16; ++uu) {
            int u = ub1 + uu;
            float a0 = CB1[u];
            float a1 = CB1[32 + u];
            float a2 = CB1[64 + u];
            float a3 = CB1[96 + u];
            const float4* w0 = reinterpret_cast<const float4*>(sw + OFF_W1IH + u * 8);
            const float4* w1 = reinterpret_cast<const float4*>(sw + OFF_W1IH + (32 + u) * 8);
            const float4* w2 = reinterpret_cast<const float4*>(sw + OFF_W1IH + (64 + u) * 8);
            const float4* w3 = reinterpret_cast<const float4*>(sw + OFF_W1IH + (96 + u) * 8);
#pragma unroll
            for (int d = 0; d < 2; ++d) {
                float4 q0 = w0[d], q1 = w1[d], q2 = w2[d], q3 = w3[d];
                float x0 = xr[4 * d + 0], x1 = xr[4 * d + 1];
                float x2 = xr[4 * d + 2], x3 = xr[4 * d + 3];
                a0 = fmaf(x0, q0.x, a0); a1 = fmaf(x0, q1.x, a1);
                a2 = fmaf(x0, q2.x, a2); a3 = fmaf(x0, q3.x, a3);
                a0 = fmaf(x1, q0.y, a0); a1 = fmaf(x1, q1.y, a1);
                a2 = fmaf(x1, q2.y, a2); a3 = fmaf(x1, q3.y, a3);
                a0 = fmaf(x2, q0.z, a0); a1 = fmaf(x2, q1.z, a1);
                a2 = fmaf(x2, q2.z, a2); a3 = fmaf(x2, q3.z, a3);
                a0 = fmaf(x3, q0.w, a0); a1 = fmaf(x3, q1.w, a1);
                a2 = fmaf(x3, q2.w, a2); a3 = fmaf(x3, q3.w, a3);
            }
            // hh: gate i -> const row u, gate f -> const row 32+u,
            //     gate g -> smem local row u, gate o -> smem local row 32+u
            const float4* vg = reinterpret_cast<const float4*>(sw + OFF_W1HGO + u * 32);
            const float4* vo = reinterpret_cast<const float4*>(sw + OFF_W1HGO + (32 + u) * 32);
#pragma unroll
            for (int j = 0; j < 8; ++j) {
                float4 qi = C_E1HH_IF[u * 8 + j];
                float4 qf = C_E1HH_IF[(32 + u) * 8 + j];
                float4 qg = vg[j];
                float4 qo = vo[j];
                float p0 = h1[4 * j + 0], p1 = h1[4 * j + 1];
                float p2 = h1[4 * j + 2], p3 = h1[4 * j + 3];
                a0 = fmaf(p0, qi.x, a0); a1 = fmaf(p0, qf.x, a1);
                a2 = fmaf(p0, qg.x, a2); a3 = fmaf(p0, qo.x, a3);
                a0 = fmaf(p1, qi.y, a0); a1 = fmaf(p1, qf.y, a1);
                a2 = fmaf(p1, qg.y, a2); a3 = fmaf(p1, qo.y, a3);
                a0 = fmaf(p2, qi.z, a0); a1 = fmaf(p2, qf.z, a1);
                a2 = fmaf(p2, qg.z, a2); a3 = fmaf(p2, qo.z, a3);
                a0 = fmaf(p3, qi.w, a0); a1 = fmaf(p3, qf.w, a1);
                a2 = fmaf(p3, qg.w, a2); a3 = fmaf(p3, qo.w, a3);
            }
            float ig = sigf(a0);
            float fg = sigf(a1);
            float gg = tanhx(a2);
            float og = sigf(a3);
            float cn = fmaf(fg, c1l[uu], ig * gg);
            c1l[uu] = cn;
            sw[OFF_H1B + u * 32 + lane] = og * tanhx(cn);
        }
        __syncthreads();
#pragma unroll
        for (int j = 0; j < 32; ++j) h1[j] = sw[OFF_H1B + j * 32 + lane];

        // ---- e2: my 4 units, ih from CONST, hh from SMEM ----
#pragma unroll 1
        for (int uu = 0; uu < 4; ++uu) {
            int u = ub2 + uu;
            float a0 = CB2[u];
            float a1 = CB2[8 + u];
            float a2 = CB2[16 + u];
            float a3 = CB2[24 + u];
#pragma unroll
            for (int d = 0; d < 8; ++d) {
                float4 q0 = C_E2IH[u * 8 + d];
                float4 q1 = C_E2IH[(8 + u) * 8 + d];
                float4 q2 = C_E2IH[(16 + u) * 8 + d];
                float4 q3 = C_E2IH[(24 + u) * 8 + d];
                float p0 = h1[4 * d + 0], p1 = h1[4 * d + 1];
                float p2 = h1[4 * d + 2], p3 = h1[4 * d + 3];
                a0 = fmaf(p0, q0.x, a0); a1 = fmaf(p0, q1.x, a1);
                a2 = fmaf(p0, q2.x, a2); a3 = fmaf(p0, q3.x, a3);
                a0 = fmaf(p1, q0.y, a0); a1 = fmaf(p1, q1.y, a1);
                a2 = fmaf(p1, q2.y, a2); a3 = fmaf(p1, q3.y, a3);
                a0 = fmaf(p2, q0.z, a0); a1 = fmaf(p2, q1.z, a1);
                a2 = fmaf(p2, q2.z, a2); a3 = fmaf(p2, q3.z, a3);
                a0 = fmaf(p3, q0.w, a0); a1 = fmaf(p3, q1.w, a1);
                a2 = fmaf(p3, q2.w, a2); a3 = fmaf(p3, q3.w, a3);
            }
            const float4* v0 = reinterpret_cast<const float4*>(sw + OFF_W2HH + u * 8);
            const float4* v1 = reinterpret_cast<const float4*>(sw + OFF_W2HH + (8 + u) * 8);
            const float4* v2 = reinterpret_cast<const float4*>(sw + OFF_W2HH + (16 + u) * 8);
            const float4* v3 = reinterpret_cast<const float4*>(sw + OFF_W2HH + (24 + u) * 8);
#pragma unroll
            for (int j = 0; j < 2; ++j) {
                float4 q0 = v0[j], q1 = v1[j], q2 = v2[j], q3 = v3[j];
                float p0 = h2[4 * j + 0], p1 = h2[4 * j + 1];
                float p2 = h2[4 * j + 2], p3 = h2[4 * j + 3];
                a0 = fmaf(p0, q0.x, a0); a1 = fmaf(p0, q1.x, a1);
                a2 = fmaf(p0, q2.x, a2); a3 = fmaf(p0, q3.x, a3);
                a0 = fmaf(p1, q0.y, a0); a1 = fmaf(p1, q1.y, a1);
                a2 = fmaf(p1, q2.y, a2); a3 = fmaf(p1, q3.y, a3);
                a0 = fmaf(p2, q0.z, a0); a1 = fmaf(p2, q1.z, a1);
                a2 = fmaf(p2, q2.z, a2); a3 = fmaf(p2, q3.z, a3);
                a0 = fmaf(p3, q0.w, a0); a1 = fmaf(p3, q1.w, a1);
                a2 = fmaf(p3, q2.w, a2); a3 = fmaf(p3, q3.w, a3);
            }
            float ig = sigf(a0);
            float fg = sigf(a1);
            float gg = tanhx(a2);
            float og = sigf(a3);
            float cn = fmaf(fg, c2l[uu], ig * gg);
            c2l[uu] = cn;
            sw[OFF_H2B + u * 32 + lane] = og * tanhx(cn);
        }
        __syncthreads();
#pragma unroll
        for (int j = 0; j < 8; ++j) h2[j] = sw[OFF_H2B + j * 32 + lane];

        // ---- e3 + decoder + fc on half 0 only ----
        if (half == 0) {
            lstm_small<1, 8>(sw + OFF_W3IH, sw + OFF_W3HH, sw + OFF_B3, h2, h3, c3);
            float dv[1] = { h3[0] };
            lstm_small<2, 1>(sw + OFF_D1IH, sw + OFF_D1HH, sw + OFF_BD1, dv, hd1, cd1);
            lstm_small<2, 2>(sw + OFF_D2IH, sw + OFF_D2HH, sw + OFF_BD2, hd1, hd2, cd2);
            lstm_small<1, 2>(sw + OFF_D3IH, sw + OFF_D3HH, sw + OFF_BD3, hd2, hd3, cd3);
            float y = hd3[0];
            const float* gr = sw + OFF_G + t * 12;
#pragma unroll
            for (int j = 0; j < 12; ++j) acc[j] = fmaf(y, gr[j], acc[j]);
        }
    }

    // ---- aux steps + epilogue: half 0 only ----
    if (half == 0) {
#pragma unroll 1
        for (int t = T; t < 60; ++t) {
            float dv[1] = { xe[(t - 12) * 8 + 4] };
            lstm_small<2, 1>(sw + OFF_D1IH, sw + OFF_D1HH, sw + OFF_BD1, dv, hd1, cd1);
            lstm_small<2, 2>(sw + OFF_D2IH, sw + OFF_D2HH, sw + OFF_BD2, hd1, hd2, cd2);
            lstm_small<1, 2>(sw + OFF_D3IH, sw + OFF_D3HH, sw + OFF_BD3, hd2, hd3, cd3);
            float y = hd3[0];
            const float* gr = sw + OFF_G + t * 12;
#pragma unroll
            for (int j = 0; j < 12; ++j) acc[j] = fmaf(y, gr[j], acc[j]);
        }
        float r[12];
#pragma unroll
        for (int j = 0; j < 12; ++j) r[j] = acc[j] + sw[OFF_CB + j];
        float4* op = reinterpret_cast<float4*>(out + (size_t)elem * 12);
        op[0] = make_float4(r[0], r[1], r[2], r[3]);
        op[1] = make_float4(r[4], r[5], r[6], r[7]);
        op[2] = make_float4(r[8], r[9], r[10], r[11]);
    }
}

extern "C" void kernel_launch(void* const* d_in, const int* in_sizes, int n_in,
                              void* d_out, int out_size) {
    (void)in_sizes; (void)n_in; (void)out_size;
    const float* x    = (const float*)d_in[0];
    const float* w1ih = (const float*)d_in[1];
    const float* w1hh = (const float*)d_in[2];
    const float* b1   = (const float*)d_in[3];
    const float* w2ih = (const float*)d_in[4];
    const float* w2hh = (const float*)d_in[5];
    const float* b2   = (const float*)d_in[6];
    const float* w3ih = (const float*)d_in[7];
    const float* w3hh = (const float*)d_in[8];
    const float* b3   = (const float*)d_in[9];
    const float* d1ih = (const float*)d_in[10];
    const float* d1hh = (const float*)d_in[11];
    const float* bd1  = (const float*)d_in[12];
    const float* d2ih = (const float*)d_in[13];
    const float* d2hh = (const float*)d_in[14];
    const float* bd2  = (const float*)d_in[15];
    const float* d3ih = (const float*)d_in[16];
    const float* d3hh = (const float*)d_in[17];
    const float* bd3  = (const float*)d_in[18];
    const float* fc1w = (const float*)d_in[19];
    const float* fc1b = (const float*)d_in[20];
    const float* fc2w = (const float*)d_in[21];
    const float* fc2b = (const float*)d_in[22];
    float* out = (float*)d_out;

    // Stage const-port weights (D2D async, graph-capturable, no allocation)
    cudaMemcpyToSymbolAsync(C_E1HH_IF, w1hh, 64 * 32 * 4, 0, cudaMemcpyDeviceToDevice, 0);
    cudaMemcpyToSymbolAsync(C_E2IH, w2ih, 32 * 32 * 4, 0, cudaMemcpyDeviceToDevice, 0);
    cudaMemcpyToSymbolAsync(CB1, b1, 128 * 4, 0, cudaMemcpyDeviceToDevice, 0);
    cudaMemcpyToSymbolAsync(CB2, b2, 32 * 4, 0, cudaMemcpyDeviceToDevice, 0);

    dim3 grid(BATCH / 32);
    dim3 block(TPB);
    vd_encdec_kernel<<<grid, block>>>(
        x, w1ih, w1hh, w2hh,
        w3ih, w3hh, b3,
        d1ih, d1hh, bd1, d2ih, d2hh, bd2, d3ih, d3hh, bd3,
        fc1w, fc1b, fc2w, fc2b, out);
}

// round 13
// speedup vs baseline: 3.1250x; 3.1250x over previous
#include <cuda_runtime.h>

// VDEncoderDecoder: stacked LSTM encoder (8->32->8->1, T=48) + decoder
// (1->2->2->1, 60 steps) + fused fc via g = fc2_w @ fc1_w.
// Group of 64 batch elements per CTA (2 warps). Warp h owns e1 units
// [16h,16h+16) and e2 units [4h,4h+4); each lane processes TWO elements
// (eA = base+lane, eB = base+32+lane), so every weight float fetched from
// smem feeds 8 FMAs (4 smem-broadcast floats x 2 elements). Hidden state
// exchanged via smem + 2 syncthreads per timestep. Decoder: warp0 handles
// element A, warp1 element B (balanced). 1024 warps total.

#define TPB 64
static constexpr int BATCH = 32768;
static constexpr int T = 48;

// smem float offsets
static constexpr int OFF_W1IH = 0;       // 128x8   = 1024
static constexpr int OFF_W1HH = 1024;    // 128x32  = 4096
static constexpr int OFF_B1   = 5120;    // 128
static constexpr int OFF_W2IH = 5248;    // 32x32   = 1024
static constexpr int OFF_W2HH = 6272;    // 32x8    = 256
static constexpr int OFF_B2   = 6528;    // 32
static constexpr int OFF_W3IH = 6560;    // 32
static constexpr int OFF_W3HH = 6592;    // 4
static constexpr int OFF_B3   = 6596;    // 4
static constexpr int OFF_D1IH = 6600;    // 8
static constexpr int OFF_D1HH = 6608;    // 16
static constexpr int OFF_BD1  = 6624;    // 8
static constexpr int OFF_D2IH = 6632;    // 16
static constexpr int OFF_D2HH = 6648;    // 16
static constexpr int OFF_BD2  = 6664;    // 8
static constexpr int OFF_D3IH = 6672;    // 8
static constexpr int OFF_D3HH = 6680;    // 4
static constexpr int OFF_BD3  = 6684;    // 4
static constexpr int OFF_G    = 6688;    // 720
static constexpr int OFF_CB   = 7408;    // 12
static constexpr int OFF_H1B  = 7420;    // 32 units x 64 elems = 2048
static constexpr int OFF_H2B  = 9468;    // 8 units x 64 elems  = 512
static constexpr int SMEM_FLOATS = 9980; // 39.9 KB

__device__ __forceinline__ float sigf(float x) {
    return __fdividef(1.0f, 1.0f + __expf(-x));
}
__device__ __forceinline__ float tanhx(float x) {
    float e = __expf(2.0f * x);
    return 1.0f - __fdividef(2.0f, e + 1.0f);
}

// Small scalar LSTM cell (decoder path), fully unrolled.
template<int H, int DIN>
__device__ __forceinline__ void lstm_small(
    const float* __restrict__ wih, const float* __restrict__ whh,
    const float* __restrict__ bias,
    const float (&xin)[DIN], float (&h)[H], float (&c)[H])
{
    float hn[H];
#pragma unroll
    for (int u = 0; u < H; ++u) {
        float a0 = bias[u];
        float a1 = bias[H + u];
        float a2 = bias[2 * H + u];
        float a3 = bias[3 * H + u];
#pragma unroll
        for (int d = 0; d < DIN; ++d) {
            float xv = xin[d];
            a0 = fmaf(xv, wih[u * DIN + d], a0);
            a1 = fmaf(xv, wih[(H + u) * DIN + d], a1);
            a2 = fmaf(xv, wih[(2 * H + u) * DIN + d], a2);
            a3 = fmaf(xv, wih[(3 * H + u) * DIN + d], a3);
        }
#pragma unroll
        for (int j = 0; j < H; ++j) {
            float hv = h[j];
            a0 = fmaf(hv, whh[u * H + j], a0);
            a1 = fmaf(hv, whh[(H + u) * H + j], a1);
            a2 = fmaf(hv, whh[(2 * H + u) * H + j], a2);
            a3 = fmaf(hv, whh[(3 * H + u) * H + j], a3);
        }
        float ig = sigf(a0);
        float fg = sigf(a1);
        float gg = tanhx(a2);
        float og = sigf(a3);
        float cn = fmaf(fg, c[u], ig * gg);
        c[u] = cn;
        hn[u] = og * tanhx(cn);
    }
#pragma unroll
    for (int u = 0; u < H; ++u) h[u] = hn[u];
}

__global__ void __launch_bounds__(TPB)
vd_encdec_kernel(
    const float* __restrict__ x,
    const float* __restrict__ w1ih, const float* __restrict__ w1hh, const float* __restrict__ b1,
    const float* __restrict__ w2ih, const float* __restrict__ w2hh, const float* __restrict__ b2,
    const float* __restrict__ w3ih, const float* __restrict__ w3hh, const float* __restrict__ b3,
    const float* __restrict__ d1ih, const float* __restrict__ d1hh, const float* __restrict__ bd1,
    const float* __restrict__ d2ih, const float* __restrict__ d2hh, const float* __restrict__ bd2,
    const float* __restrict__ d3ih, const float* __restrict__ d3hh, const float* __restrict__ bd3,
    const float* __restrict__ fc1w, const float* __restrict__ fc1b,
    const float* __restrict__ fc2w, const float* __restrict__ fc2b,
    float* __restrict__ out)
{
    __shared__ __align__(16) float sw[SMEM_FLOATS];
    const int tid = threadIdx.x;

    for (int i = tid; i < 1024; i += TPB) sw[OFF_W1IH + i] = w1ih[i];
    for (int i = tid; i < 4096; i += TPB) sw[OFF_W1HH + i] = w1hh[i];
    for (int i = tid; i < 128;  i += TPB) sw[OFF_B1   + i] = b1[i];
    for (int i = tid; i < 1024; i += TPB) sw[OFF_W2IH + i] = w2ih[i];
    for (int i = tid; i < 256;  i += TPB) sw[OFF_W2HH + i] = w2hh[i];
    for (int i = tid; i < 32;   i += TPB) sw[OFF_B2   + i] = b2[i];
    for (int i = tid; i < 32;   i += TPB) sw[OFF_W3IH + i] = w3ih[i];
    if (tid < 4)  sw[OFF_W3HH + tid] = w3hh[tid];
    if (tid < 4)  sw[OFF_B3   + tid] = b3[tid];
    if (tid < 8)  sw[OFF_D1IH + tid] = d1ih[tid];
    if (tid < 16) sw[OFF_D1HH + tid] = d1hh[tid];
    if (tid < 8)  sw[OFF_BD1 + tid] = bd1[tid];
    if (tid < 16) sw[OFF_D2IH + tid] = d2ih[tid];
    if (tid < 16) sw[OFF_D2HH + tid] = d2hh[tid];
    if (tid < 8)  sw[OFF_BD2 + tid] = bd2[tid];
    if (tid < 8)  sw[OFF_D3IH + tid] = d3ih[tid];
    if (tid < 4)  sw[OFF_D3HH + tid] = d3hh[tid];
    if (tid < 4)  sw[OFF_BD3 + tid] = bd3[tid];
    for (int i = tid; i < 720; i += TPB) {
        int t = i / 12, j = i % 12;
        float a = 0.0f;
        for (int k = 0; k < 32; ++k)
            a = fmaf(fc2w[j * 32 + k], fc1w[k * 60 + t], a);
        sw[OFF_G + i] = a;
    }
    if (tid < 12) {
        float a = fc2b[tid];
        for (int k = 0; k < 32; ++k)
            a = fmaf(fc2w[tid * 32 + k], fc1b[k], a);
        sw[OFF_CB + tid] = a;
    }
    __syncthreads();

    const int lane = tid & 31;
    const int half = tid >> 5;
    const int base = blockIdx.x * 64;
    const int eA = base + lane;
    const int eB = base + 32 + lane;
    const int eD = base + 32 * half + lane;   // my decoder element
    const float* xA = x + (size_t)eA * (T * 8);
    const float* xB = x + (size_t)eB * (T * 8);
    const float* xD = x + (size_t)eD * (T * 8);
    const int ub1 = half * 16;
    const int ub2 = half * 4;

    float h1A[32], h1B[32];        // full old h1 (registers, static idx)
    float c1A[16], c1B[16];        // my units' c (runtime idx ok)
    float h2A[8], h2B[8];
    float c2A[4], c2B[4];
    float h3[1], c3[1];
    float hd1[2], cd1[2], hd2[2], cd2[2], hd3[1], cd3[1];
    float acc[12];

#pragma unroll
    for (int i = 0; i < 32; ++i) { h1A[i] = 0.0f; h1B[i] = 0.0f; }
#pragma unroll
    for (int i = 0; i < 16; ++i) { c1A[i] = 0.0f; c1B[i] = 0.0f; }
#pragma unroll
    for (int i = 0; i < 8; ++i) { h2A[i] = 0.0f; h2B[i] = 0.0f; }
#pragma unroll
    for (int i = 0; i < 4; ++i) { c2A[i] = 0.0f; c2B[i] = 0.0f; }
    h3[0] = 0.0f; c3[0] = 0.0f;
#pragma unroll
    for (int i = 0; i < 2; ++i) { hd1[i] = 0.0f; cd1[i] = 0.0f; hd2[i] = 0.0f; cd2[i] = 0.0f; }
    hd3[0] = 0.0f; cd3[0] = 0.0f;
#pragma unroll
    for (int i = 0; i < 12; ++i) acc[i] = 0.0f;

    // ---- fused steps t = 0..47 ----
#pragma unroll 1
    for (int t = 0; t < T; ++t) {
        float4 qa = *reinterpret_cast<const float4*>(xA + t * 8);
        float4 qb = *reinterpret_cast<const float4*>(xA + t * 8 + 4);
        float xrA[8] = { qa.x, qa.y, qa.z, qa.w, qb.x, qb.y, qb.z, qb.w };
        float4 ra = *reinterpret_cast<const float4*>(xB + t * 8);
        float4 rb = *reinterpret_cast<const float4*>(xB + t * 8 + 4);
        float xrB[8] = { ra.x, ra.y, ra.z, ra.w, rb.x, rb.y, rb.z, rb.w };

        // ---- e1: my 16 units, both elements ----
#pragma unroll 1
        for (int uu = 0; uu < 16; ++uu) {
            int u = ub1 + uu;
            float b0 = sw[OFF_B1 + u];
            float b1v = sw[OFF_B1 + 32 + u];
            float b2v = sw[OFF_B1 + 64 + u];
            float b3v = sw[OFF_B1 + 96 + u];
            float a0A = b0, a1A = b1v, a2A = b2v, a3A = b3v;
            float a0B = b0, a1B = b1v, a2B = b2v, a3B = b3v;
            const float4* w0 = reinterpret_cast<const float4*>(sw + OFF_W1IH + u * 8);
            const float4* w1 = reinterpret_cast<const float4*>(sw + OFF_W1IH + (32 + u) * 8);
            const float4* w2 = reinterpret_cast<const float4*>(sw + OFF_W1IH + (64 + u) * 8);
            const float4* w3 = reinterpret_cast<const float4*>(sw + OFF_W1IH + (96 + u) * 8);
#pragma unroll
            for (int d = 0; d < 2; ++d) {
                float4 q0 = w0[d], q1 = w1[d], q2 = w2[d], q3 = w3[d];
                float pA0 = xrA[4 * d + 0], pA1 = xrA[4 * d + 1];
                float pA2 = xrA[4 * d + 2], pA3 = xrA[4 * d + 3];
                float pB0 = xrB[4 * d + 0], pB1 = xrB[4 * d + 1];
                float pB2 = xrB[4 * d + 2], pB3 = xrB[4 * d + 3];
                a0A = fmaf(pA0, q0.x, a0A); a0B = fmaf(pB0, q0.x, a0B);
                a1A = fmaf(pA0, q1.x, a1A); a1B = fmaf(pB0, q1.x, a1B);
                a2A = fmaf(pA0, q2.x, a2A); a2B = fmaf(pB0, q2.x, a2B);
                a3A = fmaf(pA0, q3.x, a3A); a3B = fmaf(pB0, q3.x, a3B);
                a0A = fmaf(pA1, q0.y, a0A); a0B = fmaf(pB1, q0.y, a0B);
                a1A = fmaf(pA1, q1.y, a1A); a1B = fmaf(pB1, q1.y, a1B);
                a2A = fmaf(pA1, q2.y, a2A); a2B = fmaf(pB1, q2.y, a2B);
                a3A = fmaf(pA1, q3.y, a3A); a3B = fmaf(pB1, q3.y, a3B);
                a0A = fmaf(pA2, q0.z, a0A); a0B = fmaf(pB2, q0.z, a0B);
                a1A = fmaf(pA2, q1.z, a1A); a1B = fmaf(pB2, q1.z, a1B);
                a2A = fmaf(pA2, q2.z, a2A); a2B = fmaf(pB2, q2.z, a2B);
                a3A = fmaf(pA2, q3.z, a3A); a3B = fmaf(pB2, q3.z, a3B);
                a0A = fmaf(pA3, q0.w, a0A); a0B = fmaf(pB3, q0.w, a0B);
                a1A = fmaf(pA3, q1.w, a1A); a1B = fmaf(pB3, q1.w, a1B);
                a2A = fmaf(pA3, q2.w, a2A); a2B = fmaf(pB3, q2.w, a2B);
                a3A = fmaf(pA3, q3.w, a3A); a3B = fmaf(pB3, q3.w, a3B);
            }
            const float4* v0 = reinterpret_cast<const float4*>(sw + OFF_W1HH + u * 32);
            const float4* v1 = reinterpret_cast<const float4*>(sw + OFF_W1HH + (32 + u) * 32);
            const float4* v2 = reinterpret_cast<const float4*>(sw + OFF_W1HH + (64 + u) * 32);
            const float4* v3 = reinterpret_cast<const float4*>(sw + OFF_W1HH + (96 + u) * 32);
#pragma unroll
            for (int j = 0; j < 8; ++j) {
                float4 q0 = v0[j], q1 = v1[j], q2 = v2[j], q3 = v3[j];
                float pA0 = h1A[4 * j + 0], pA1 = h1A[4 * j + 1];
                float pA2 = h1A[4 * j + 2], pA3 = h1A[4 * j + 3];
                float pB0 = h1B[4 * j + 0], pB1 = h1B[4 * j + 1];
                float pB2 = h1B[4 * j + 2], pB3 = h1B[4 * j + 3];
                a0A = fmaf(pA0, q0.x, a0A); a0B = fmaf(pB0, q0.x, a0B);
                a1A = fmaf(pA0, q1.x, a1A); a1B = fmaf(pB0, q1.x, a1B);
                a2A = fmaf(pA0, q2.x, a2A); a2B = fmaf(pB0, q2.x, a2B);
                a3A = fmaf(pA0, q3.x, a3A); a3B = fmaf(pB0, q3.x, a3B);
                a0A = fmaf(pA1, q0.y, a0A); a0B = fmaf(pB1, q0.y, a0B);
                a1A = fmaf(pA1, q1.y, a1A); a1B = fmaf(pB1, q1.y, a1B);
                a2A = fmaf(pA1, q2.y, a2A); a2B = fmaf(pB1, q2.y, a2B);
                a3A = fmaf(pA1, q3.y, a3A); a3B = fmaf(pB1, q3.y, a3B);
                a0A = fmaf(pA2, q0.z, a0A); a0B = fmaf(pB2, q0.z, a0B);
                a1A = fmaf(pA2, q1.z, a1A); a1B = fmaf(pB2, q1.z, a1B);
                a2A = fmaf(pA2, q2.z, a2A); a2B = fmaf(pB2, q2.z, a2B);
                a3A = fmaf(pA2, q3.z, a3A); a3B = fmaf(pB2, q3.z, a3B);
                a0A = fmaf(pA3, q0.w, a0A); a0B = fmaf(pB3, q0.w, a0B);
                a1A = fmaf(pA3, q1.w, a1A); a1B = fmaf(pB3, q1.w, a1B);
                a2A = fmaf(pA3, q2.w, a2A); a2B = fmaf(pB3, q2.w, a2B);
                a3A = fmaf(pA3, q3.w, a3A); a3B = fmaf(pB3, q3.w, a3B);
            }
            {
                float ig = sigf(a0A), fg = sigf(a1A), gg = tanhx(a2A), og = sigf(a3A);
                float cn = fmaf(fg, c1A[uu], ig * gg);
                c1A[uu] = cn;
                sw[OFF_H1B + u * 64 + lane] = og * tanhx(cn);
            }
            {
                float ig = sigf(a0B), fg = sigf(a1B), gg = tanhx(a2B), og = sigf(a3B);
                float cn = fmaf(fg, c1B[uu], ig * gg);
                c1B[uu] = cn;
                sw[OFF_H1B + u * 64 + 32 + lane] = og * tanhx(cn);
            }
        }
        __syncthreads();
#pragma unroll
        for (int j = 0; j < 32; ++j) {
            h1A[j] = sw[OFF_H1B + j * 64 + lane];
            h1B[j] = sw[OFF_H1B + j * 64 + 32 + lane];
        }

        // ---- e2: my 4 units, both elements ----
#pragma unroll 1
        for (int uu = 0; uu < 4; ++uu) {
            int u = ub2 + uu;
            float b0 = sw[OFF_B2 + u];
            float b1v = sw[OFF_B2 + 8 + u];
            float b2v = sw[OFF_B2 + 16 + u];
            float b3v = sw[OFF_B2 + 24 + u];
            float a0A = b0, a1A = b1v, a2A = b2v, a3A = b3v;
            float a0B = b0, a1B = b1v, a2B = b2v, a3B = b3v;
            const float4* w0 = reinterpret_cast<const float4*>(sw + OFF_W2IH + u * 32);
            const float4* w1 = reinterpret_cast<const float4*>(sw + OFF_W2IH + (8 + u) * 32);
            const float4* w2 = reinterpret_cast<const float4*>(sw + OFF_W2IH + (16 + u) * 32);
            const float4* w3 = reinterpret_cast<const float4*>(sw + OFF_W2IH + (24 + u) * 32);
#pragma unroll
            for (int d = 0; d < 8; ++d) {
                float4 q0 = w0[d], q1 = w1[d], q2 = w2[d], q3 = w3[d];
                float pA0 = h1A[4 * d + 0], pA1 = h1A[4 * d + 1];
                float pA2 = h1A[4 * d + 2], pA3 = h1A[4 * d + 3];
                float pB0 = h1B[4 * d + 0], pB1 = h1B[4 * d + 1];
                float pB2 = h1B[4 * d + 2], pB3 = h1B[4 * d + 3];
                a0A = fmaf(pA0, q0.x, a0A); a0B = fmaf(pB0, q0.x, a0B);
                a1A = fmaf(pA0, q1.x, a1A); a1B = fmaf(pB0, q1.x, a1B);
                a2A = fmaf(pA0, q2.x, a2A); a2B = fmaf(pB0, q2.x, a2B);
                a3A = fmaf(pA0, q3.x, a3A); a3B = fmaf(pB0, q3.x, a3B);
                a0A = fmaf(pA1, q0.y, a0A); a0B = fmaf(pB1, q0.y, a0B);
                a1A = fmaf(pA1, q1.y, a1A); a1B = fmaf(pB1, q1.y, a1B);
                a2A = fmaf(pA1, q2.y, a2A); a2B = fmaf(pB1, q2.y, a2B);
                a3A = fmaf(pA1, q3.y, a3A); a3B = fmaf(pB1, q3.y, a3B);
                a0A = fmaf(pA2, q0.z, a0A); a0B = fmaf(pB2, q0.z, a0B);
                a1A = fmaf(pA2, q1.z, a1A); a1B = fmaf(pB2, q1.z, a1B);
                a2A = fmaf(pA2, q2.z, a2A); a2B = fmaf(pB2, q2.z, a2B);
                a3A = fmaf(pA2, q3.z, a3A); a3B = fmaf(pB2, q3.z, a3B);
                a0A = fmaf(pA3, q0.w, a0A); a0B = fmaf(pB3, q0.w, a0B);
                a1A = fmaf(pA3, q1.w, a1A); a1B = fmaf(pB3, q1.w, a1B);
                a2A = fmaf(pA3, q2.w, a2A); a2B = fmaf(pB3, q2.w, a2B);
                a3A = fmaf(pA3, q3.w, a3A); a3B = fmaf(pB3, q3.w, a3B);
            }
            const float4* v0 = reinterpret_cast<const float4*>(sw + OFF_W2HH + u * 8);
            const float4* v1 = reinterpret_cast<const float4*>(sw + OFF_W2HH + (8 + u) * 8);
            const float4* v2 = reinterpret_cast<const float4*>(sw + OFF_W2HH + (16 + u) * 8);
            const float4* v3 = reinterpret_cast<const float4*>(sw + OFF_W2HH + (24 + u) * 8);
#pragma unroll
            for (int j = 0; j < 2; ++j) {
                float4 q0 = v0[j], q1 = v1[j], q2 = v2[j], q3 = v3[j];
                float pA0 = h2A[4 * j + 0], pA1 = h2A[4 * j + 1];
                float pA2 = h2A[4 * j + 2], pA3 = h2A[4 * j + 3];
                float pB0 = h2B[4 * j + 0], pB1 = h2B[4 * j + 1];
                float pB2 = h2B[4 * j + 2], pB3 = h2B[4 * j + 3];
                a0A = fmaf(pA0, q0.x, a0A); a0B = fmaf(pB0, q0.x, a0B);
                a1A = fmaf(pA0, q1.x, a1A); a1B = fmaf(pB0, q1.x, a1B);
                a2A = fmaf(pA0, q2.x, a2A); a2B = fmaf(pB0, q2.x, a2B);
                a3A = fmaf(pA0, q3.x, a3A); a3B = fmaf(pB0, q3.x, a3B);
                a0A = fmaf(pA1, q0.y, a0A); a0B = fmaf(pB1, q0.y, a0B);
                a1A = fmaf(pA1, q1.y, a1A); a1B = fmaf(pB1, q1.y, a1B);
                a2A = fmaf(pA1, q2.y, a2A); a2B = fmaf(pB1, q2.y, a2B);
                a3A = fmaf(pA1, q3.y, a3A); a3B = fmaf(pB1, q3.y, a3B);
                a0A = fmaf(pA2, q0.z, a0A); a0B = fmaf(pB2, q0.z, a0B);
                a1A = fmaf(pA2, q1.z, a1A); a1B = fmaf(pB2, q1.z, a1B);
                a2A = fmaf(pA2, q2.z, a2A); a2B = fmaf(pB2, q2.z, a2B);
                a3A = fmaf(pA2, q3.z, a3A); a3B = fmaf(pB2, q3.z, a3B);
                a0A = fmaf(pA3, q0.w, a0A); a0B = fmaf(pB3, q0.w, a0B);
                a1A = fmaf(pA3, q1.w, a1A); a1B = fmaf(pB3, q1.w, a1B);
                a2A = fmaf(pA3, q2.w, a2A); a2B = fmaf(pB3, q2.w, a2B);
                a3A = fmaf(pA3, q3.w, a3A); a3B = fmaf(pB3, q3.w, a3B);
            }
            {
                float ig = sigf(a0A), fg = sigf(a1A), gg = tanhx(a2A), og = sigf(a3A);
                float cn = fmaf(fg, c2A[uu], ig * gg);
                c2A[uu] = cn;
                sw[OFF_H2B + u * 64 + lane] = og * tanhx(cn);
            }
            {
                float ig = sigf(a0B), fg = sigf(a1B), gg = tanhx(a2B), og = sigf(a3B);
                float cn = fmaf(fg, c2B[uu], ig * gg);
                c2B[uu] = cn;
                sw[OFF_H2B + u * 64 + 32 + lane] = og * tanhx(cn);
            }
        }
        __syncthreads();
#pragma unroll
        for (int j = 0; j < 8; ++j) {
            h2A[j] = sw[OFF_H2B + j * 64 + lane];
            h2B[j] = sw[OFF_H2B + j * 64 + 32 + lane];
        }

        // ---- decoder: warp0 -> element A, warp1 -> element B ----
        float h2d[8];
#pragma unroll
        for (int j = 0; j < 8; ++j) h2d[j] = (half == 0) ? h2A[j] : h2B[j];
        lstm_small<1, 8>(sw + OFF_W3IH, sw + OFF_W3HH, sw + OFF_B3, h2d, h3, c3);
        float dv[1] = { h3[0] };
        lstm_small<2, 1>(sw + OFF_D1IH, sw + OFF_D1HH, sw + OFF_BD1, dv, hd1, cd1);
        lstm_small<2, 2>(sw + OFF_D2IH, sw + OFF_D2HH, sw + OFF_BD2, hd1, hd2, cd2);
        lstm_small<1, 2>(sw + OFF_D3IH, sw + OFF_D3HH, sw + OFF_BD3, hd2, hd3, cd3);
        float y = hd3[0];
        const float* gr = sw + OFF_G + t * 12;
#pragma unroll
        for (int j = 0; j < 12; ++j) acc[j] = fmaf(y, gr[j], acc[j]);
    }

    // ---- aux steps t = 48..59: decoder input = x[eD, t-12, 4] ----
#pragma unroll 1
    for (int t = T; t < 60; ++t) {
        float dv[1] = { xD[(t - 12) * 8 + 4] };
        lstm_small<2, 1>(sw + OFF_D1IH, sw + OFF_D1HH, sw + OFF_BD1, dv, hd1, cd1);
        lstm_small<2, 2>(sw + OFF_D2IH, sw + OFF_D2HH, sw + OFF_BD2, hd1, hd2, cd2);
        lstm_small<1, 2>(sw + OFF_D3IH, sw + OFF_D3HH, sw + OFF_BD3, hd2, hd3, cd3);
        float y = hd3[0];
        const float* gr = sw + OFF_G + t * 12;
#pragma unroll
        for (int j = 0; j < 12; ++j) acc[j] = fmaf(y, gr[j], acc[j]);
    }

    // ---- epilogue: out[eD] ----
    float r[12];
#pragma unroll
    for (int j = 0; j < 12; ++j) r[j] = acc[j] + sw[OFF_CB + j];
    float4* op = reinterpret_cast<float4*>(out + (size_t)eD * 12);
    op[0] = make_float4(r[0], r[1], r[2], r[3]);
    op[1] = make_float4(r[4], r[5], r[6], r[7]);
    op[2] = make_float4(r[8], r[9], r[10], r[11]);
}

extern "C" void kernel_launch(void* const* d_in, const int* in_sizes, int n_in,
                              void* d_out, int out_size) {
    (void)in_sizes; (void)n_in; (void)out_size;
    const float* x    = (const float*)d_in[0];
    const float* w1ih = (const float*)d_in[1];
    const float* w1hh = (const float*)d_in[2];
    const float* b1   = (const float*)d_in[3];
    const float* w2ih = (const float*)d_in[4];
    const float* w2hh = (const float*)d_in[5];
    const float* b2   = (const float*)d_in[6];
    const float* w3ih = (const float*)d_in[7];
    const float* w3hh = (const float*)d_in[8];
    const float* b3   = (const float*)d_in[9];
    const float* d1ih = (const float*)d_in[10];
    const float* d1hh = (const float*)d_in[11];
    const float* bd1  = (const float*)d_in[12];
    const float* d2ih = (const float*)d_in[13];
    const float* d2hh = (const float*)d_in[14];
    const float* bd2  = (const float*)d_in[15];
    const float* d3ih = (const float*)d_in[16];
    const float* d3hh = (const float*)d_in[17];
    const float* bd3  = (const float*)d_in[18];
    const float* fc1w = (const float*)d_in[19];
    const float* fc1b = (const float*)d_in[20];
    const float* fc2w = (const float*)d_in[21];
    const float* fc2b = (const float*)d_in[22];
    float* out = (float*)d_out;

    dim3 grid(BATCH / 64);   // 64 elements (2 warps) per CTA
    dim3 block(TPB);
    vd_encdec_kernel<<<grid, block>>>(
        x, w1ih, w1hh, b1, w2ih, w2hh, b2, w3ih, w3hh, b3,
        d1ih, d1hh, bd1, d2ih, d2hh, bd2, d3ih, d3hh, bd3,
        fc1w, fc1b, fc2w, fc2b, out);
}